// round 2
// baseline (speedup 1.0000x reference)
#include <cuda_runtime.h>
#include <cuda_bf16.h>

// FilterLayer: out = irfft(rfft(x, ortho) * W, ortho) + x  over last dim (L=12)
// == per-node circulant matvec: out[t] = sum_j h'[n][(t-j) mod 12] * x[j],
// residual identity folded into tap d=0.
//
// R2: smem-staged, fully coalesced global traffic. The 48B-per-row layout makes
// direct per-row LDG.128 hit 12 L1 wavefronts/instr (measured binding at
// ~6300 B/cyc chip-wide). Staging via smem makes all LDG/STG unit-stride
// (4 wf/instr); the 48B-stride LDS.128/STS.128 are bank-conflict-free
// (8 lanes x 48B mod 128B = 8 distinct 16B slots).

#define SEQ 12
#define NODES 207
#define NFREQ 7
#define TPB 256
#define NTAPS (NODES * SEQ)   // 2484

__device__ __align__(16) float g_H[NTAPS];

__device__ __constant__ double c_COS[12] = {
    1.0,  0.8660254037844387,  0.5,  0.0, -0.5, -0.8660254037844387,
   -1.0, -0.8660254037844387, -0.5,  0.0,  0.5,  0.8660254037844387
};
__device__ __constant__ double c_SIN[12] = {
    0.0,  0.5,  0.8660254037844387,  1.0,  0.8660254037844387,  0.5,
    0.0, -0.5, -0.8660254037844387, -1.0, -0.8660254037844387, -0.5
};

__global__ void build_taps_kernel(const float* __restrict__ w /*[207][7][2]*/) {
    int i = blockIdx.x * blockDim.x + threadIdx.x;
    if (i >= NTAPS) return;
    int n = i / SEQ;
    int d = i % SEQ;
    const float* wn = w + n * (NFREQ * 2);

    double acc = (double)wn[0];                               // Re(W0)
    acc += ((d & 1) ? -1.0 : 1.0) * (double)wn[2 * 6];        // (-1)^d Re(W6)
    #pragma unroll
    for (int k = 1; k <= 5; k++) {
        int m = (k * d) % 12;
        acc += 2.0 * ((double)wn[2 * k] * c_COS[m] - (double)wn[2 * k + 1] * c_SIN[m]);
    }
    float h = (float)(acc / 12.0);
    if (d == 0) h += 1.0f;                                    // fold residual
    g_H[i] = h;
}

__global__ void __launch_bounds__(TPB) filter_apply_kernel(
    const float4* __restrict__ x, float4* __restrict__ out)
{
    __shared__ __align__(16) float s_H[NTAPS];
    __shared__ float4 s_buf[TPB * 3];

    const int tid = threadIdx.x;
    const int r   = blockIdx.x * TPB + tid;           // my row (grid is exact)
    const size_t base4 = (size_t)blockIdx.x * (TPB * 3);

    // cooperative tap load (coalesced; 9.9 KB)
    #pragma unroll
    for (int i = tid; i < NTAPS; i += TPB) s_H[i] = g_H[i];

    // stage input chunk, unit-stride LDG.128
    #pragma unroll
    for (int k = 0; k < 3; k++)
        s_buf[tid + k * TPB] = x[base4 + tid + k * TPB];
    __syncthreads();

    // per-row reads: 48B-stride LDS.128, conflict-free
    float4 a = s_buf[tid * 3 + 0];
    float4 b = s_buf[tid * 3 + 1];
    float4 c = s_buf[tid * 3 + 2];
    float xv[SEQ] = { a.x, a.y, a.z, a.w,  b.x, b.y, b.z, b.w,  c.x, c.y, c.z, c.w };

    const int n = r % NODES;
    const float4* hp = reinterpret_cast<const float4*>(s_H + n * SEQ);
    float4 h0 = hp[0], h1 = hp[1], h2 = hp[2];
    float h[SEQ] = { h0.x, h0.y, h0.z, h0.w,  h1.x, h1.y, h1.z, h1.w,
                     h2.x, h2.y, h2.z, h2.w };

    float y[SEQ];
    #pragma unroll
    for (int t = 0; t < SEQ; t++) {
        float s = 0.0f;
        #pragma unroll
        for (int j = 0; j < SEQ; j++)
            s = fmaf(h[(t - j + SEQ) % SEQ], xv[j], s);   // compile-time index
        y[t] = s;
    }

    __syncthreads();   // protect s_buf reuse

    // stage output: 48B-stride STS.128, conflict-free
    s_buf[tid * 3 + 0] = make_float4(y[0], y[1], y[2],  y[3]);
    s_buf[tid * 3 + 1] = make_float4(y[4], y[5], y[6],  y[7]);
    s_buf[tid * 3 + 2] = make_float4(y[8], y[9], y[10], y[11]);
    __syncthreads();

    // unit-stride STG.128
    #pragma unroll
    for (int k = 0; k < 3; k++)
        out[base4 + tid + k * TPB] = s_buf[tid + k * TPB];
}

extern "C" void kernel_launch(void* const* d_in, const int* in_sizes, int n_in,
                              void* d_out, int out_size) {
    const float* x = (const float*)d_in[0];   // [1024,32,207,12] fp32
    const float* w = (const float*)d_in[1];   // [1,207,7,2] fp32
    float* out = (float*)d_out;

    build_taps_kernel<<<(NTAPS + 255) / 256, 256>>>(w);

    int nrows = out_size / SEQ;               // 6,782,976 = 26496 * 256 exactly
    int blocks = (nrows + TPB - 1) / TPB;
    filter_apply_kernel<<<blocks, TPB>>>(
        reinterpret_cast<const float4*>(x),
        reinterpret_cast<float4*>(d_out ? (float4*)out : nullptr));
}

// round 3
// speedup vs baseline: 1.0355x; 1.0355x over previous
#include <cuda_runtime.h>
#include <cuda_bf16.h>

// FilterLayer: out = irfft(rfft(x, ortho)*W, ortho) + x over last dim (L=12)
// == per-node circulant matvec, residual folded into tap d=0.
//
// R3: trio/shuffle scheme. 3 lanes co-own a row; each lane does exactly one
// coalesced LDG.128 + one coalesced STG.128 per row-iteration. Row gathered
// via warp shuffles. Taps are register-resident for the whole kernel: the
// grid-stride (596160 rows) is a multiple of 207, so a lane's node is fixed.

#define SEQ 12
#define NODES 207
#define NFREQ 7
#define NTAPS (NODES * SEQ)

#define TPB 256
#define NBLOCKS 7452                    // 59,616 warps
#define NWARPS (NBLOCKS * TPB / 32)     // 59,616
#define ROWS_PER_WARP 10
#define SWEEP (NWARPS * ROWS_PER_WARP)  // 596,160 = 207 * 2880 (node-preserving)

__device__ __align__(16) float g_H[NTAPS];

__device__ __constant__ double c_COS[12] = {
    1.0,  0.8660254037844387,  0.5,  0.0, -0.5, -0.8660254037844387,
   -1.0, -0.8660254037844387, -0.5,  0.0,  0.5,  0.8660254037844387
};
__device__ __constant__ double c_SIN[12] = {
    0.0,  0.5,  0.8660254037844387,  1.0,  0.8660254037844387,  0.5,
    0.0, -0.5, -0.8660254037844387, -1.0, -0.8660254037844387, -0.5
};

__global__ void build_taps_kernel(const float* __restrict__ w /*[207][7][2]*/) {
    int i = blockIdx.x * blockDim.x + threadIdx.x;
    if (i >= NTAPS) return;
    int n = i / SEQ, d = i % SEQ;
    const float* wn = w + n * (NFREQ * 2);
    double acc = (double)wn[0];
    acc += ((d & 1) ? -1.0 : 1.0) * (double)wn[2 * 6];
    #pragma unroll
    for (int k = 1; k <= 5; k++) {
        int m = (k * d) % 12;
        acc += 2.0 * ((double)wn[2 * k] * c_COS[m] - (double)wn[2 * k + 1] * c_SIN[m]);
    }
    float h = (float)(acc / 12.0);
    if (d == 0) h += 1.0f;
    g_H[i] = h;
}

__device__ __forceinline__ float4 shfl_f4(float4 v, int src) {
    float4 r;
    r.x = __shfl_sync(0xFFFFFFFFu, v.x, src);
    r.y = __shfl_sync(0xFFFFFFFFu, v.y, src);
    r.z = __shfl_sync(0xFFFFFFFFu, v.z, src);
    r.w = __shfl_sync(0xFFFFFFFFu, v.w, src);
    return r;
}

__global__ void __launch_bounds__(TPB) filter_apply_kernel(
    const float4* __restrict__ x, float4* __restrict__ out, int nrows)
{
    const int tid  = blockIdx.x * TPB + threadIdx.x;
    const int w    = tid >> 5;          // global warp id
    const int lane = tid & 31;
    const int sub  = lane / 3;          // row slot within warp (0..9, 10 = idle)
    const int part = lane % 3;          // which third of the row
    const int t0   = part * 4;          // this lane's output offset
    const bool lane_ok = (lane < 30);

    // Node for this lane is invariant across the grid-stride (SWEEP % 207 == 0).
    const int r0 = w * ROWS_PER_WARP + sub;       // first row this lane serves
    const int node = r0 % NODES;

    // Load taps once, rotated left by t0 (float4-granular rotation).
    float hr[SEQ];
    {
        const float4* Hv = reinterpret_cast<const float4*>(g_H + node * SEQ);
        float4 A = __ldg(Hv + 0), B = __ldg(Hv + 1), C = __ldg(Hv + 2);
        float4 R0 = A, R1 = B, R2 = C;
        if (t0 == 4) { R0 = B; R1 = C; R2 = A; }
        if (t0 == 8) { R0 = C; R1 = A; R2 = B; }
        hr[0]=R0.x; hr[1]=R0.y; hr[2] =R0.z; hr[3] =R0.w;
        hr[4]=R1.x; hr[5]=R1.y; hr[6] =R1.z; hr[7] =R1.w;
        hr[8]=R2.x; hr[9]=R2.y; hr[10]=R2.z; hr[11]=R2.w;
    }

    const int lb = lane - part;   // trio base lane

    for (int rbase = w * ROWS_PER_WARP; rbase < nrows; rbase += SWEEP) {
        const int row = rbase + sub;
        const bool ok = lane_ok && (row < nrows);

        // Coalesced load: lane l takes float4 index rbase*3 + lane (dense 480B/warp)
        float4 v = make_float4(0.f, 0.f, 0.f, 0.f);
        const long gidx = (long)rbase * 3 + lane;
        if (ok) v = __ldg(x + gidx);

        // Gather full row from the trio (all lanes converged at the shuffles)
        float4 va = shfl_f4(v, lb);
        float4 vb = shfl_f4(v, lb + 1);
        float4 vc = shfl_f4(v, lb + 2);
        float xv[SEQ] = { va.x, va.y, va.z, va.w,
                          vb.x, vb.y, vb.z, vb.w,
                          vc.x, vc.y, vc.z, vc.w };

        // This lane's 4 outputs: y[t0+i] = sum_j hr[(i-j) mod 12] * x[j]
        float y[4];
        #pragma unroll
        for (int i = 0; i < 4; i++) {
            float s = 0.0f;
            #pragma unroll
            for (int j = 0; j < SEQ; j++)
                s = fmaf(hr[(i - j + SEQ) % SEQ], xv[j], s);
            y[i] = s;
        }

        if (ok) out[gidx] = make_float4(y[0], y[1], y[2], y[3]);
    }
}

extern "C" void kernel_launch(void* const* d_in, const int* in_sizes, int n_in,
                              void* d_out, int out_size) {
    const float* x = (const float*)d_in[0];   // [1024,32,207,12] fp32
    const float* w = (const float*)d_in[1];   // [1,207,7,2] fp32

    build_taps_kernel<<<(NTAPS + 255) / 256, 256>>>(w);

    int nrows = out_size / SEQ;               // 6,782,976
    filter_apply_kernel<<<NBLOCKS, TPB>>>(
        reinterpret_cast<const float4*>(x),
        reinterpret_cast<float4*>(d_out),
        nrows);
}